// round 10
// baseline (speedup 1.0000x reference)
#include <cuda_runtime.h>
#include <cstdint>

// ============================================================================
// LoRADense: out = x @ W + bias + (x . A[id]) . B[id]
//   x:(8192,1024)f32  ids:(8192,)i32  W:(1024,1024)f32  bias:(1024,)f32
//   lora_a:(64,1024,16)f32  lora_b:(64,16,1024)f32
//
// R9 = R8 resubmit (infra failure last round):
//   L1: rv[n] = x[n] . A[id[n]]   (A^T in smem, conflict-free, 4 CTA/adapter)
//   L2: out[n] += rv[n] . B[id[n]] (B in smem, float4 RMW, 4 CTA/adapter)
// GEMM: R5 cp.async mma.sync tf32 design (~65us measured).
// ============================================================================

#define N_TOK 8192
#define DIM   1024
#define FEAT  1024

__device__ float g_wt[FEAT * DIM];     // W^T tf32-rounded (4 MB)
__device__ float g_rv[N_TOK * 16];     // low-rank intermediate (512 KB)

__device__ __forceinline__ uint32_t to_tf32(float v) {
    uint32_t o;
    asm("cvt.rna.tf32.f32 %0, %1;" : "=r"(o) : "f"(v));
    return o;
}
__device__ __forceinline__ void cp16(uint32_t dst, const void* src) {
    asm volatile("cp.async.cg.shared.global [%0], [%1], 16;" :: "r"(dst), "l"(src));
}
__device__ __forceinline__ uint32_t smem_u32(const void* p) {
    uint32_t a;
    asm("{ .reg .u64 t; cvta.to.shared.u64 t, %1; cvt.u32.u64 %0, t; }"
        : "=r"(a) : "l"(p));
    return a;
}
__device__ __forceinline__ void mma_tf32(float& c0, float& c1, float& c2, float& c3,
                                         uint32_t a0, uint32_t a1, uint32_t a2, uint32_t a3,
                                         uint32_t b0, uint32_t b1) {
    asm volatile(
        "mma.sync.aligned.m16n8k8.row.col.f32.tf32.tf32.f32 "
        "{%0,%1,%2,%3}, {%4,%5,%6,%7}, {%8,%9}, {%0,%1,%2,%3};"
        : "+f"(c0), "+f"(c1), "+f"(c2), "+f"(c3)
        : "r"(a0), "r"(a1), "r"(a2), "r"(a3), "r"(b0), "r"(b1));
}

// ============================================================================
// Kernel 1: W (D,F) -> g_wt (F,D), tf32-rounded
// ============================================================================
__global__ void transpose_w_kernel(const float* __restrict__ W) {
    __shared__ float t[32][33];
    int fx = blockIdx.x * 32 + threadIdx.x;
    int dy = blockIdx.y * 32 + threadIdx.y;
#pragma unroll
    for (int i = 0; i < 32; i += 8)
        t[threadIdx.y + i][threadIdx.x] = W[(size_t)(dy + i) * FEAT + fx];
    __syncthreads();
    int dx = blockIdx.y * 32 + threadIdx.x;
    int fy = blockIdx.x * 32 + threadIdx.y;
#pragma unroll
    for (int i = 0; i < 32; i += 8)
        g_wt[(size_t)(fy + i) * DIM + dx] =
            __uint_as_float(to_tf32(t[threadIdx.x][threadIdx.y + i]));
}

// ============================================================================
// Kernel 2: tf32 GEMM, BM=256 BN=128 BK=32, 256 thr, 64x64 warp tiles
// ============================================================================
static constexpr int BM = 256, BN = 128, BK = 32;
static constexpr int AS = 36;
static constexpr int NKCH = DIM / BK;
static constexpr int DEPTH = 3;
static constexpr int A_FLOATS = BM * AS;
static constexpr int B_FLOATS = BN * AS;
static constexpr int STAGE_FLOATS = A_FLOATS + B_FLOATS;
static constexpr int GEMM_SMEM = DEPTH * STAGE_FLOATS * 4;   // 165888 B

__device__ __forceinline__ void load_stage(uint32_t sb, int slot, int kc,
                                           const float* __restrict__ x,
                                           int mbase, int nbase, int tid) {
    uint32_t baseA = sb + (uint32_t)(slot * STAGE_FLOATS) * 4u;
    uint32_t baseB = baseA + (uint32_t)A_FLOATS * 4u;
    const float* xp = x    + (size_t)mbase * DIM + kc * BK;
    const float* wp = g_wt + (size_t)nbase * DIM + kc * BK;
#pragma unroll
    for (int it = 0; it < 8; it++) {
        int c  = tid + it * 256;
        int r  = c >> 3, cc = c & 7;
        cp16(baseA + (uint32_t)(r * AS + cc * 4) * 4u, xp + (size_t)r * DIM + cc * 4);
    }
#pragma unroll
    for (int it = 0; it < 4; it++) {
        int c  = tid + it * 256;
        int r  = c >> 3, cc = c & 7;
        cp16(baseB + (uint32_t)(r * AS + cc * 4) * 4u, wp + (size_t)r * DIM + cc * 4);
    }
}

__global__ void __launch_bounds__(256, 1)
gemm_tf32_kernel(const float* __restrict__ x, const float* __restrict__ bias,
                 float* __restrict__ out) {
    extern __shared__ float smem[];
    uint32_t sb = smem_u32(smem);

    const int tid = threadIdx.x;
    const int wid = tid >> 5, lane = tid & 31;
    const int wm = wid >> 1, wn = wid & 1;
    const int qr = lane >> 2, qc = lane & 3;
    const int mbase = blockIdx.x * BM;
    const int nbase = blockIdx.y * BN;

    float acc[4][8][4];
#pragma unroll
    for (int mi = 0; mi < 4; mi++)
#pragma unroll
        for (int ni = 0; ni < 8; ni++)
#pragma unroll
            for (int q = 0; q < 4; q++) acc[mi][ni][q] = 0.f;

    load_stage(sb, 0, 0, x, mbase, nbase, tid);
    asm volatile("cp.async.commit_group;" ::: "memory");
    load_stage(sb, 1, 1, x, mbase, nbase, tid);
    asm volatile("cp.async.commit_group;" ::: "memory");

#pragma unroll 1
    for (int i = 0; i < NKCH; i++) {
        if (i >= NKCH - 1) asm volatile("cp.async.wait_group 0;" ::: "memory");
        else               asm volatile("cp.async.wait_group 1;" ::: "memory");
        __syncthreads();

        if (i + 2 < NKCH) {
            load_stage(sb, (i + 2) % DEPTH, i + 2, x, mbase, nbase, tid);
            asm volatile("cp.async.commit_group;" ::: "memory");
        }

        const int slot = i % DEPTH;
        const uint32_t* As = (const uint32_t*)(smem + slot * STAGE_FLOATS);
        const uint32_t* Bs = As + A_FLOATS;

#pragma unroll
        for (int ks = 0; ks < 4; ks++) {
            const int kb = ks * 8;
            uint32_t a[4][4];
#pragma unroll
            for (int mi = 0; mi < 4; mi++) {
                int row = wm * 64 + mi * 16 + qr;
                a[mi][0] = As[row * AS + kb + qc];
                a[mi][1] = As[(row + 8) * AS + kb + qc];
                a[mi][2] = As[row * AS + kb + qc + 4];
                a[mi][3] = As[(row + 8) * AS + kb + qc + 4];
            }
            uint32_t b[8][2];
#pragma unroll
            for (int ni = 0; ni < 8; ni++) {
                int col = wn * 64 + ni * 8 + qr;
                b[ni][0] = Bs[col * AS + kb + qc];
                b[ni][1] = Bs[col * AS + kb + qc + 4];
            }
#pragma unroll
            for (int mi = 0; mi < 4; mi++)
#pragma unroll
                for (int ni = 0; ni < 8; ni++)
                    mma_tf32(acc[mi][ni][0], acc[mi][ni][1],
                             acc[mi][ni][2], acc[mi][ni][3],
                             a[mi][0], a[mi][1], a[mi][2], a[mi][3],
                             b[ni][0], b[ni][1]);
        }
    }

#pragma unroll
    for (int mi = 0; mi < 4; mi++) {
        int row0 = mbase + wm * 64 + mi * 16 + qr;
#pragma unroll
        for (int ni = 0; ni < 8; ni++) {
            int col = nbase + wn * 64 + ni * 8 + 2 * qc;
            float bx = bias[col], by = bias[col + 1];
            float2 v0 = make_float2(acc[mi][ni][0] + bx, acc[mi][ni][1] + by);
            float2 v1 = make_float2(acc[mi][ni][2] + bx, acc[mi][ni][3] + by);
            *(float2*)(out + (size_t)row0 * FEAT + col)       = v0;
            *(float2*)(out + (size_t)(row0 + 8) * FEAT + col) = v1;
        }
    }
}

// ============================================================================
// Kernel 3 (L1): rv[n] = x[n] . A[id[n]].  4 CTAs/adapter (token n%4 split).
//   A^T in smem: A_sT[r][d], stride 1032 -> bank (8r+lane)%32, conflict-free.
// ============================================================================
static constexpr int ATS = DIM + 8;                       // 1032
static constexpr int L1_SMEM = 16 * ATS * 4 + 2048 * 4 + 64;   // ~74 KB

__global__ void __launch_bounds__(256, 2)
lora_rv_kernel(const float* __restrict__ x, const int* __restrict__ ids,
               const float* __restrict__ lora_a) {
    extern __shared__ char dsm[];
    float* A_sT = (float*)dsm;              // [16][ATS]
    int*   list = (int*)(A_sT + 16 * ATS);  // [2048]
    int*   cnt  = list + 2048;

    const int tid  = threadIdx.x;
    const int warp = tid >> 5, lane = tid & 31;
    const int slot = blockIdx.x >> 2;
    const int sub  = blockIdx.x & 3;

    if (tid == 0) *cnt = 0;

    // A[slot] (d-major, 1024x16) -> A_sT[r][d]
    {
        const float* ap = lora_a + (size_t)slot * DIM * 16;
        for (int i = tid; i < DIM * 16; i += 256) {
            int d = i >> 4, r = i & 15;
            A_sT[r * ATS + d] = ap[i];
        }
    }
    __syncthreads();

    for (int m = tid; m < N_TOK / 4; m += 256) {
        int n = 4 * m + sub;
        if (ids[n] == slot) list[atomicAdd(cnt, 1)] = n;
    }
    __syncthreads();
    const int total = *cnt;

    for (int i = warp; i < total; i += 8) {
        const int n = list[i];
        const float* xr = x + (size_t)n * DIM;

        float xv[32];
#pragma unroll
        for (int k = 0; k < 32; k++) xv[k] = xr[k * 32 + lane];

        float acc[16];
#pragma unroll
        for (int r = 0; r < 16; r++) acc[r] = 0.f;
#pragma unroll
        for (int k = 0; k < 32; k++) {
            const int d = k * 32 + lane;
            float xd = xv[k];
#pragma unroll
            for (int r = 0; r < 16; r++)
                acc[r] = fmaf(xd, A_sT[r * ATS + d], acc[r]);
        }
#pragma unroll
        for (int r = 0; r < 16; r++) {
#pragma unroll
            for (int o = 16; o > 0; o >>= 1)
                acc[r] += __shfl_xor_sync(0xFFFFFFFFu, acc[r], o);
        }
        if (lane == 0) {
            float4* rv4 = (float4*)(g_rv + (size_t)n * 16);
            rv4[0] = make_float4(acc[0],  acc[1],  acc[2],  acc[3]);
            rv4[1] = make_float4(acc[4],  acc[5],  acc[6],  acc[7]);
            rv4[2] = make_float4(acc[8],  acc[9],  acc[10], acc[11]);
            rv4[3] = make_float4(acc[12], acc[13], acc[14], acc[15]);
        }
    }
}

// ============================================================================
// Kernel 4 (L2): out[n] += rv[n] . B[id[n]].  4 CTAs/adapter.
//   B in smem (lane-consecutive float4 reads, conflict-free), float4 RMW.
// ============================================================================
static constexpr int L2_SMEM = 16 * FEAT * 4 + 2048 * 4 + 64;   // ~72 KB

__global__ void __launch_bounds__(256, 2)
lora_out_kernel(const int* __restrict__ ids, const float* __restrict__ lora_b,
                float* __restrict__ out) {
    extern __shared__ char dsm[];
    float* B_s  = (float*)dsm;              // [16][1024]
    int*   list = (int*)(B_s + 16 * FEAT);  // [2048]
    int*   cnt  = list + 2048;

    const int tid  = threadIdx.x;
    const int warp = tid >> 5, lane = tid & 31;
    const int slot = blockIdx.x >> 2;
    const int sub  = blockIdx.x & 3;

    if (tid == 0) *cnt = 0;

    {
        const float4* bp = (const float4*)(lora_b + (size_t)slot * 16 * FEAT);
        float4* bs = (float4*)B_s;
        for (int i = tid; i < 16 * FEAT / 4; i += 256) bs[i] = bp[i];
    }
    __syncthreads();

    for (int m = tid; m < N_TOK / 4; m += 256) {
        int n = 4 * m + sub;
        if (ids[n] == slot) list[atomicAdd(cnt, 1)] = n;
    }
    __syncthreads();
    const int total = *cnt;

    const float4* B4 = (const float4*)B_s;

    for (int i = warp; i < total; i += 8) {
        const int n = list[i];
        const float4* rv4 = (const float4*)(g_rv + (size_t)n * 16);
        float4 r0 = rv4[0], r1 = rv4[1], r2 = rv4[2], r3 = rv4[3];
        float rv[16] = { r0.x, r0.y, r0.z, r0.w,  r1.x, r1.y, r1.z, r1.w,
                         r2.x, r2.y, r2.z, r2.w,  r3.x, r3.y, r3.z, r3.w };

        float4* orow = (float4*)(out + (size_t)n * FEAT);
#pragma unroll
        for (int j = 0; j < 8; j++) {
            int f4 = j * 32 + lane;
            float4 v = orow[f4];
#pragma unroll
            for (int r = 0; r < 16; r++) {
                float4 b = B4[r * 256 + f4];
                v.x = fmaf(rv[r], b.x, v.x);
                v.y = fmaf(rv[r], b.y, v.y);
                v.z = fmaf(rv[r], b.z, v.z);
                v.w = fmaf(rv[r], b.w, v.w);
            }
            orow[f4] = v;
        }
    }
}

// ============================================================================
// Launch
// ============================================================================
extern "C" void kernel_launch(void* const* d_in, const int* in_sizes, int n_in,
                              void* d_out, int out_size) {
    const float* x      = (const float*)d_in[0];
    const int*   ids    = (const int*)d_in[1];
    const float* W      = (const float*)d_in[2];
    const float* bias   = (const float*)d_in[3];
    const float* lora_a = (const float*)d_in[4];
    const float* lora_b = (const float*)d_in[5];
    float* out = (float*)d_out;

    cudaFuncSetAttribute(gemm_tf32_kernel,
                         cudaFuncAttributeMaxDynamicSharedMemorySize, GEMM_SMEM);
    cudaFuncSetAttribute(lora_rv_kernel,
                         cudaFuncAttributeMaxDynamicSharedMemorySize, L1_SMEM);
    cudaFuncSetAttribute(lora_out_kernel,
                         cudaFuncAttributeMaxDynamicSharedMemorySize, L2_SMEM);

    dim3 tgrid(FEAT / 32, DIM / 32);
    transpose_w_kernel<<<tgrid, dim3(32, 8)>>>(W);

    lora_rv_kernel<<<256, 256, L1_SMEM>>>(x, ids, lora_a);

    dim3 ggrid(N_TOK / BM, FEAT / BN);   // 32 x 8
    gemm_tf32_kernel<<<ggrid, 256, GEMM_SMEM>>>(x, bias, out);

    lora_out_kernel<<<256, 256, L2_SMEM>>>(ids, lora_b, out);
}

// round 11
// speedup vs baseline: 2.1420x; 2.1420x over previous
#include <cuda_runtime.h>
#include <cstdint>

// ============================================================================
// LoRADense: out = x @ W + bias + (x . A[id]) . B[id]
//   x:(8192,1024)f32  ids:(8192,)i32  W:(1024,1024)f32  bias:(1024,)f32
//   lora_a:(64,1024,16)f32  lora_b:(64,16,1024)f32
//
// R11:
//   L1 (rv = x.A[id]): adapter-major, A^T in smem (conflict-free),
//       2 tokens/warp (crossbar amortized), butterfly reduce -> g_rv
//   GEMM: R5/R7 cp.async mma.sync tf32 (unchanged, ~65us)
//   L2 (out += rv.B[id]): TOKEN-MAJOR streaming — warp-per-token in order,
//       B via __ldg from L2, no smem/lists/atomics, coalesced RMW of out
// ============================================================================

#define N_TOK 8192
#define DIM   1024
#define FEAT  1024

__device__ float g_wt[FEAT * DIM];     // W^T tf32-rounded (4 MB)
__device__ float g_rv[N_TOK * 16];     // low-rank intermediate (512 KB)

__device__ __forceinline__ uint32_t to_tf32(float v) {
    uint32_t o;
    asm("cvt.rna.tf32.f32 %0, %1;" : "=r"(o) : "f"(v));
    return o;
}
__device__ __forceinline__ void cp16(uint32_t dst, const void* src) {
    asm volatile("cp.async.cg.shared.global [%0], [%1], 16;" :: "r"(dst), "l"(src));
}
__device__ __forceinline__ uint32_t smem_u32(const void* p) {
    uint32_t a;
    asm("{ .reg .u64 t; cvta.to.shared.u64 t, %1; cvt.u32.u64 %0, t; }"
        : "=r"(a) : "l"(p));
    return a;
}
__device__ __forceinline__ void mma_tf32(float& c0, float& c1, float& c2, float& c3,
                                         uint32_t a0, uint32_t a1, uint32_t a2, uint32_t a3,
                                         uint32_t b0, uint32_t b1) {
    asm volatile(
        "mma.sync.aligned.m16n8k8.row.col.f32.tf32.tf32.f32 "
        "{%0,%1,%2,%3}, {%4,%5,%6,%7}, {%8,%9}, {%0,%1,%2,%3};"
        : "+f"(c0), "+f"(c1), "+f"(c2), "+f"(c3)
        : "r"(a0), "r"(a1), "r"(a2), "r"(a3), "r"(b0), "r"(b1));
}

// ============================================================================
// Kernel 1: W (D,F) -> g_wt (F,D), tf32-rounded
// ============================================================================
__global__ void transpose_w_kernel(const float* __restrict__ W) {
    __shared__ float t[32][33];
    int fx = blockIdx.x * 32 + threadIdx.x;
    int dy = blockIdx.y * 32 + threadIdx.y;
#pragma unroll
    for (int i = 0; i < 32; i += 8)
        t[threadIdx.y + i][threadIdx.x] = W[(size_t)(dy + i) * FEAT + fx];
    __syncthreads();
    int dx = blockIdx.y * 32 + threadIdx.x;
    int fy = blockIdx.x * 32 + threadIdx.y;
#pragma unroll
    for (int i = 0; i < 32; i += 8)
        g_wt[(size_t)(fy + i) * DIM + dx] =
            __uint_as_float(to_tf32(t[threadIdx.x][threadIdx.y + i]));
}

// ============================================================================
// Kernel 2: tf32 GEMM, BM=256 BN=128 BK=32, 256 thr, 64x64 warp tiles
// ============================================================================
static constexpr int BM = 256, BN = 128, BK = 32;
static constexpr int AS = 36;
static constexpr int NKCH = DIM / BK;
static constexpr int DEPTH = 3;
static constexpr int A_FLOATS = BM * AS;
static constexpr int B_FLOATS = BN * AS;
static constexpr int STAGE_FLOATS = A_FLOATS + B_FLOATS;
static constexpr int GEMM_SMEM = DEPTH * STAGE_FLOATS * 4;   // 165888 B

__device__ __forceinline__ void load_stage(uint32_t sb, int slot, int kc,
                                           const float* __restrict__ x,
                                           int mbase, int nbase, int tid) {
    uint32_t baseA = sb + (uint32_t)(slot * STAGE_FLOATS) * 4u;
    uint32_t baseB = baseA + (uint32_t)A_FLOATS * 4u;
    const float* xp = x    + (size_t)mbase * DIM + kc * BK;
    const float* wp = g_wt + (size_t)nbase * DIM + kc * BK;
#pragma unroll
    for (int it = 0; it < 8; it++) {
        int c  = tid + it * 256;
        int r  = c >> 3, cc = c & 7;
        cp16(baseA + (uint32_t)(r * AS + cc * 4) * 4u, xp + (size_t)r * DIM + cc * 4);
    }
#pragma unroll
    for (int it = 0; it < 4; it++) {
        int c  = tid + it * 256;
        int r  = c >> 3, cc = c & 7;
        cp16(baseB + (uint32_t)(r * AS + cc * 4) * 4u, wp + (size_t)r * DIM + cc * 4);
    }
}

__global__ void __launch_bounds__(256, 1)
gemm_tf32_kernel(const float* __restrict__ x, const float* __restrict__ bias,
                 float* __restrict__ out) {
    extern __shared__ float smem[];
    uint32_t sb = smem_u32(smem);

    const int tid = threadIdx.x;
    const int wid = tid >> 5, lane = tid & 31;
    const int wm = wid >> 1, wn = wid & 1;
    const int qr = lane >> 2, qc = lane & 3;
    const int mbase = blockIdx.x * BM;
    const int nbase = blockIdx.y * BN;

    float acc[4][8][4];
#pragma unroll
    for (int mi = 0; mi < 4; mi++)
#pragma unroll
        for (int ni = 0; ni < 8; ni++)
#pragma unroll
            for (int q = 0; q < 4; q++) acc[mi][ni][q] = 0.f;

    load_stage(sb, 0, 0, x, mbase, nbase, tid);
    asm volatile("cp.async.commit_group;" ::: "memory");
    load_stage(sb, 1, 1, x, mbase, nbase, tid);
    asm volatile("cp.async.commit_group;" ::: "memory");

#pragma unroll 1
    for (int i = 0; i < NKCH; i++) {
        if (i >= NKCH - 1) asm volatile("cp.async.wait_group 0;" ::: "memory");
        else               asm volatile("cp.async.wait_group 1;" ::: "memory");
        __syncthreads();

        if (i + 2 < NKCH) {
            load_stage(sb, (i + 2) % DEPTH, i + 2, x, mbase, nbase, tid);
            asm volatile("cp.async.commit_group;" ::: "memory");
        }

        const int slot = i % DEPTH;
        const uint32_t* As = (const uint32_t*)(smem + slot * STAGE_FLOATS);
        const uint32_t* Bs = As + A_FLOATS;

#pragma unroll
        for (int ks = 0; ks < 4; ks++) {
            const int kb = ks * 8;
            uint32_t a[4][4];
#pragma unroll
            for (int mi = 0; mi < 4; mi++) {
                int row = wm * 64 + mi * 16 + qr;
                a[mi][0] = As[row * AS + kb + qc];
                a[mi][1] = As[(row + 8) * AS + kb + qc];
                a[mi][2] = As[row * AS + kb + qc + 4];
                a[mi][3] = As[(row + 8) * AS + kb + qc + 4];
            }
            uint32_t b[8][2];
#pragma unroll
            for (int ni = 0; ni < 8; ni++) {
                int col = wn * 64 + ni * 8 + qr;
                b[ni][0] = Bs[col * AS + kb + qc];
                b[ni][1] = Bs[col * AS + kb + qc + 4];
            }
#pragma unroll
            for (int mi = 0; mi < 4; mi++)
#pragma unroll
                for (int ni = 0; ni < 8; ni++)
                    mma_tf32(acc[mi][ni][0], acc[mi][ni][1],
                             acc[mi][ni][2], acc[mi][ni][3],
                             a[mi][0], a[mi][1], a[mi][2], a[mi][3],
                             b[ni][0], b[ni][1]);
        }
    }

#pragma unroll
    for (int mi = 0; mi < 4; mi++) {
        int row0 = mbase + wm * 64 + mi * 16 + qr;
#pragma unroll
        for (int ni = 0; ni < 8; ni++) {
            int col = nbase + wn * 64 + ni * 8 + 2 * qc;
            float bx = bias[col], by = bias[col + 1];
            float2 v0 = make_float2(acc[mi][ni][0] + bx, acc[mi][ni][1] + by);
            float2 v1 = make_float2(acc[mi][ni][2] + bx, acc[mi][ni][3] + by);
            *(float2*)(out + (size_t)row0 * FEAT + col)       = v0;
            *(float2*)(out + (size_t)(row0 + 8) * FEAT + col) = v1;
        }
    }
}

// ============================================================================
// Kernel 3 (L1): rv[n] = x[n] . A[id[n]].  4 CTAs/adapter, 2 tokens/warp.
//   A^T smem: A_sT[r][d], stride 1032 -> bank (8r+lane)%32, conflict-free.
// ============================================================================
static constexpr int ATS = DIM + 8;                            // 1032
static constexpr int L1_SMEM = 16 * ATS * 4 + 2048 * 4 + 64;   // ~74 KB

__global__ void __launch_bounds__(256, 2)
lora_rv_kernel(const float* __restrict__ x, const int* __restrict__ ids,
               const float* __restrict__ lora_a) {
    extern __shared__ char dsm[];
    float* A_sT = (float*)dsm;              // [16][ATS]
    int*   list = (int*)(A_sT + 16 * ATS);  // [2048]
    int*   cnt  = list + 2048;

    const int tid  = threadIdx.x;
    const int warp = tid >> 5, lane = tid & 31;
    const int slot = blockIdx.x >> 2;
    const int sub  = blockIdx.x & 3;

    if (tid == 0) *cnt = 0;

    {   // A[slot] (d-major 1024x16) -> A_sT[r][d]
        const float* ap = lora_a + (size_t)slot * DIM * 16;
        for (int i = tid; i < DIM * 16; i += 256) {
            int d = i >> 4, r = i & 15;
            A_sT[r * ATS + d] = ap[i];
        }
    }
    __syncthreads();

    for (int m = tid; m < N_TOK / 4; m += 256) {
        int n = 4 * m + sub;
        if (ids[n] == slot) list[atomicAdd(cnt, 1)] = n;
    }
    __syncthreads();
    const int total = *cnt;

    for (int i = warp * 2; i < total; i += 16) {
        const int n0 = list[i];
        const bool has1 = (i + 1 < total);
        const int n1 = has1 ? list[i + 1] : n0;
        const float* x0 = x + (size_t)n0 * DIM;
        const float* x1 = x + (size_t)n1 * DIM;

        float xv0[32], xv1[32];
#pragma unroll
        for (int k = 0; k < 32; k++) {
            xv0[k] = x0[k * 32 + lane];
            xv1[k] = x1[k * 32 + lane];
        }

        float a0[16], a1[16];
#pragma unroll
        for (int r = 0; r < 16; r++) { a0[r] = 0.f; a1[r] = 0.f; }
#pragma unroll
        for (int k = 0; k < 32; k++) {
            const int d = k * 32 + lane;
#pragma unroll
            for (int r = 0; r < 16; r++) {
                float av = A_sT[r * ATS + d];
                a0[r] = fmaf(xv0[k], av, a0[r]);
                a1[r] = fmaf(xv1[k], av, a1[r]);
            }
        }
#pragma unroll
        for (int r = 0; r < 16; r++) {
#pragma unroll
            for (int o = 16; o > 0; o >>= 1) {
                a0[r] += __shfl_xor_sync(0xFFFFFFFFu, a0[r], o);
                a1[r] += __shfl_xor_sync(0xFFFFFFFFu, a1[r], o);
            }
        }
        if (lane == 0) {
            float4* rv0 = (float4*)(g_rv + (size_t)n0 * 16);
            rv0[0] = make_float4(a0[0],  a0[1],  a0[2],  a0[3]);
            rv0[1] = make_float4(a0[4],  a0[5],  a0[6],  a0[7]);
            rv0[2] = make_float4(a0[8],  a0[9],  a0[10], a0[11]);
            rv0[3] = make_float4(a0[12], a0[13], a0[14], a0[15]);
            if (has1) {
                float4* rv1 = (float4*)(g_rv + (size_t)n1 * 16);
                rv1[0] = make_float4(a1[0],  a1[1],  a1[2],  a1[3]);
                rv1[1] = make_float4(a1[4],  a1[5],  a1[6],  a1[7]);
                rv1[2] = make_float4(a1[8],  a1[9],  a1[10], a1[11]);
                rv1[3] = make_float4(a1[12], a1[13], a1[14], a1[15]);
            }
        }
    }
}

// ============================================================================
// Kernel 4 (L2): out[n] += rv[n] . B[id[n]].  TOKEN-MAJOR streaming:
//   warp-per-token in order, B via __ldg (L2-hot 4MB), coalesced RMW.
// ============================================================================
__global__ void __launch_bounds__(256)
lora_out_kernel(const int* __restrict__ ids, const float* __restrict__ lora_b,
                float* __restrict__ out) {
    const int warp = threadIdx.x >> 5, lane = threadIdx.x & 31;
    const int n = blockIdx.x * 8 + warp;          // grid = 1024 -> n in [0,8192)
    const int id = __ldg(ids + n);

    const float* rvp = g_rv + (size_t)n * 16;
    float rv[16];
#pragma unroll
    for (int r = 0; r < 16; r++) rv[r] = __ldg(rvp + r);   // broadcast

    const float4* B4 = (const float4*)(lora_b + (size_t)id * 16 * FEAT);
    float4* o4 = (float4*)(out + (size_t)n * FEAT);

#pragma unroll
    for (int j = 0; j < 8; j++) {
        const int f4 = j * 32 + lane;
        float4 v = o4[f4];
#pragma unroll
        for (int r = 0; r < 16; r++) {
            float4 b = __ldg(B4 + r * 256 + f4);
            v.x = fmaf(rv[r], b.x, v.x);
            v.y = fmaf(rv[r], b.y, v.y);
            v.z = fmaf(rv[r], b.z, v.z);
            v.w = fmaf(rv[r], b.w, v.w);
        }
        o4[f4] = v;
    }
}

// ============================================================================
// Launch
// ============================================================================
extern "C" void kernel_launch(void* const* d_in, const int* in_sizes, int n_in,
                              void* d_out, int out_size) {
    const float* x      = (const float*)d_in[0];
    const int*   ids    = (const int*)d_in[1];
    const float* W      = (const float*)d_in[2];
    const float* bias   = (const float*)d_in[3];
    const float* lora_a = (const float*)d_in[4];
    const float* lora_b = (const float*)d_in[5];
    float* out = (float*)d_out;

    cudaFuncSetAttribute(gemm_tf32_kernel,
                         cudaFuncAttributeMaxDynamicSharedMemorySize, GEMM_SMEM);
    cudaFuncSetAttribute(lora_rv_kernel,
                         cudaFuncAttributeMaxDynamicSharedMemorySize, L1_SMEM);

    dim3 tgrid(FEAT / 32, DIM / 32);
    transpose_w_kernel<<<tgrid, dim3(32, 8)>>>(W);

    lora_rv_kernel<<<256, 256, L1_SMEM>>>(x, ids, lora_a);

    dim3 ggrid(N_TOK / BM, FEAT / BN);   // 32 x 8
    gemm_tf32_kernel<<<ggrid, 256, GEMM_SMEM>>>(x, bias, out);

    lora_out_kernel<<<1024, 256>>>(ids, lora_b, out);
}